// round 1
// baseline (speedup 1.0000x reference)
#include <cuda_runtime.h>
#include <cuda_bf16.h>
#include <cstdint>
#include <cstddef>

// Problem dims (fixed by setup_inputs)
#define BATCH 4
#define DIM   128
#define DIN   256
#define HH    64
#define WW    64
#define HW    4096      // 64*64
#define LSEQ  4096
#define DSTATE 16
#define DTRANK 8
#define EPSV  1e-5f
#define SLOPE 0.01f

// ---------------- scratch (device globals; no allocation allowed) ----------------
struct Scratch {
    float h1[BATCH * DIN * HW];      // conv1 out / inorm1 out
    float h2[BATCH * DIM * HW];      // conv2 out / inorm2+resid out
    float t [BATCH * LSEQ * DIM];    // layernorm out, row-major (b*l, c)
    float xr[BATCH * LSEQ * 2*DIN];  // in_proj out: [xs | res]
    float xs[BATCH * LSEQ * DIN];    // conv1d+silu out
    float xdbl[BATCH * LSEQ * (DTRANK + 2*DSTATE)]; // 40 cols
    float delta[BATCH * LSEQ * DIN];
    float y [BATCH * LSEQ * DIN];
    float gated[BATCH * LSEQ * DIN];
};
__device__ Scratch g_scratch;

// ---------------- conv2d 3x3 pad 1 (direct, smem-tiled) ----------------
// Tile: 32 (x) x 16 (y) outputs, 256 threads (each thread: rows ty, ty+8),
// 16 output channels per block, 8 input channels per smem chunk.
template<int CIN, int COUT>
__global__ __launch_bounds__(256)
void conv3x3_kernel(const float* __restrict__ x, const float* __restrict__ w,
                    const float* __restrict__ bias, float* __restrict__ out)
{
    constexpr int TW = 32, TH = 16, OCPB = 16, CIC = 8;
    __shared__ float sx[CIC][TH + 2][TW + 4];   // padded rows (36) vs 34 used
    __shared__ float sw[OCPB][CIC][9];

    const int tid = threadIdx.x;
    const int tx = tid & 31, ty = tid >> 5;     // ty in 0..7
    const int bx0 = blockIdx.x * TW, by0 = blockIdx.y * TH;
    const int bz = blockIdx.z;
    const int b  = bz / (COUT / OCPB);
    const int oc0 = (bz % (COUT / OCPB)) * OCPB;

    const float* xb = x + (size_t)b * CIN * HW;

    float acc[2][OCPB];
#pragma unroll
    for (int i = 0; i < OCPB; i++) { acc[0][i] = 0.f; acc[1][i] = 0.f; }

    for (int c0 = 0; c0 < CIN; c0 += CIC) {
        __syncthreads();
        // load input patch (CIC x 18 x 34) with zero padding
        for (int idx = tid; idx < CIC * (TH + 2) * (TW + 2); idx += 256) {
            int ci  = idx / ((TH + 2) * (TW + 2));
            int rem = idx % ((TH + 2) * (TW + 2));
            int py  = rem / (TW + 2), px = rem % (TW + 2);
            int gy = by0 + py - 1, gx = bx0 + px - 1;
            float v = 0.f;
            if ((unsigned)gy < (unsigned)HH && (unsigned)gx < (unsigned)WW)
                v = xb[((size_t)(c0 + ci) * HH + gy) * WW + gx];
            sx[ci][py][px] = v;
        }
        // load weights (OCPB x CIC x 9)
        for (int idx = tid; idx < OCPB * CIC * 9; idx += 256) {
            int oc = idx / (CIC * 9);
            int r  = idx % (CIC * 9);
            int ci = r / 9, tap = r % 9;
            sw[oc][ci][tap] = w[((size_t)(oc0 + oc) * CIN + c0 + ci) * 9 + tap];
        }
        __syncthreads();

#pragma unroll
        for (int ci = 0; ci < CIC; ci++) {
            float xv[6][3];
#pragma unroll
            for (int i = 0; i < 3; i++)
#pragma unroll
                for (int j = 0; j < 3; j++) {
                    xv[i][j]     = sx[ci][ty + i][tx + j];
                    xv[i + 3][j] = sx[ci][ty + 8 + i][tx + j];
                }
#pragma unroll
            for (int oc = 0; oc < OCPB; oc++) {
                const float* wp = sw[oc][ci];
                float a0 = acc[0][oc], a1 = acc[1][oc];
#pragma unroll
                for (int t9 = 0; t9 < 9; t9++) {
                    float wv = wp[t9];
                    a0 = fmaf(xv[t9 / 3][t9 % 3], wv, a0);
                    a1 = fmaf(xv[3 + t9 / 3][t9 % 3], wv, a1);
                }
                acc[0][oc] = a0; acc[1][oc] = a1;
            }
        }
    }

    float* ob = out + (size_t)b * COUT * HW;
#pragma unroll
    for (int oc = 0; oc < OCPB; oc++) {
        float bv = bias[oc0 + oc];
        ob[((size_t)(oc0 + oc) * HH + by0 + ty)     * WW + bx0 + tx] = acc[0][oc] + bv;
        ob[((size_t)(oc0 + oc) * HH + by0 + ty + 8) * WW + bx0 + tx] = acc[1][oc] + bv;
    }
}

// ---------------- instance norm + leaky residual (+ optional outer residual) ----
// h = (h - mean)/sqrt(var+eps) + leaky_relu(h) [+ resid]
// one block per (b, c) plane of 4096 elements
__global__ __launch_bounds__(256)
void inorm_lrelu_kernel(const float* __restrict__ in, float* __restrict__ out,
                        const float* __restrict__ resid)
{
    __shared__ float s1[256], s2[256];
    const size_t base = (size_t)blockIdx.x * HW;
    const float* p = in + base;
    float v[16];
    float sum = 0.f, sq = 0.f;
#pragma unroll
    for (int i = 0; i < 16; i++) {
        v[i] = p[threadIdx.x + i * 256];
        sum += v[i]; sq += v[i] * v[i];
    }
    s1[threadIdx.x] = sum; s2[threadIdx.x] = sq;
    __syncthreads();
    for (int off = 128; off; off >>= 1) {
        if (threadIdx.x < off) {
            s1[threadIdx.x] += s1[threadIdx.x + off];
            s2[threadIdx.x] += s2[threadIdx.x + off];
        }
        __syncthreads();
    }
    float mean = s1[0] * (1.f / HW);
    float var  = s2[0] * (1.f / HW) - mean * mean;
    float rstd = rsqrtf(var + EPSV);
    float* o = out + base;
    const float* r = resid ? resid + base : nullptr;
#pragma unroll
    for (int i = 0; i < 16; i++) {
        float xv = v[i];
        float lr = xv > 0.f ? xv : SLOPE * xv;
        float val = (xv - mean) * rstd + lr;
        if (r) val += r[threadIdx.x + i * 256];
        o[threadIdx.x + i * 256] = val;
    }
}

// ---------------- layernorm over channels + transpose to (b*l, c) ----------------
// in: h[b][c][l] (c = DIM), out: t[(b*LSEQ + l)][c]
__global__ __launch_bounds__(256)
void layernorm_kernel(const float* __restrict__ h, const float* __restrict__ g,
                      const float* __restrict__ beta, float* __restrict__ t)
{
    int warp = threadIdx.x >> 5, lane = threadIdx.x & 31;
    int row = blockIdx.x * 8 + warp;            // 0 .. 16383
    int b = row >> 12, l = row & 4095;
    const float* hb = h + (size_t)b * DIM * HW + l;
    float v[4];
    float sum = 0.f, sq = 0.f;
#pragma unroll
    for (int k = 0; k < 4; k++) {
        v[k] = hb[(size_t)(lane + 32 * k) * HW];
        sum += v[k]; sq += v[k] * v[k];
    }
#pragma unroll
    for (int off = 16; off; off >>= 1) {
        sum += __shfl_xor_sync(0xffffffffu, sum, off);
        sq  += __shfl_xor_sync(0xffffffffu, sq,  off);
    }
    float mean = sum * (1.f / DIM);
    float var  = sq * (1.f / DIM) - mean * mean;
    float rstd = rsqrtf(var + EPSV);
    float* to = t + (size_t)row * DIM;
#pragma unroll
    for (int k = 0; k < 4; k++) {
        int c = lane + 32 * k;
        to[c] = (v[k] - mean) * rstd * g[c] + beta[c];
    }
}

// ---------------- fp32 SGEMM: C[M,N] = A[M,K] @ W[K,N], 128x128 tile ----------------
// TRANS=1 writes C transposed into NCHW output: out[(b*N + col)*LSEQ + l]
template<int TRANS>
__global__ __launch_bounds__(256)
void gemm128_kernel(const float* __restrict__ A, const float* __restrict__ Bw,
                    float* __restrict__ C, int M, int N, int K)
{
    __shared__ float As[8][128];
    __shared__ float Bs[8][128];
    const int tid = threadIdx.x;
    const int tm = tid >> 4, tn = tid & 15;
    const int m0 = blockIdx.x * 128, n0 = blockIdx.y * 128;

    float acc[8][8];
#pragma unroll
    for (int i = 0; i < 8; i++)
#pragma unroll
        for (int j = 0; j < 8; j++) acc[i][j] = 0.f;

    const int ar = tid >> 1, ak = (tid & 1) * 4;
    const int bk = tid >> 5, bn = (tid & 31) * 4;

    for (int k0 = 0; k0 < K; k0 += 8) {
        float4 av = *(const float4*)(A + (size_t)(m0 + ar) * K + k0 + ak);
        float4 bv = *(const float4*)(Bw + (size_t)(k0 + bk) * N + n0 + bn);
        __syncthreads();
        As[ak + 0][ar] = av.x; As[ak + 1][ar] = av.y;
        As[ak + 2][ar] = av.z; As[ak + 3][ar] = av.w;
        *(float4*)&Bs[bk][bn] = bv;
        __syncthreads();
#pragma unroll
        for (int k = 0; k < 8; k++) {
            float a[8], bb[8];
            *(float4*)(a)     = *(const float4*)&As[k][tm * 8];
            *(float4*)(a + 4) = *(const float4*)&As[k][tm * 8 + 4];
            *(float4*)(bb)     = *(const float4*)&Bs[k][tn * 8];
            *(float4*)(bb + 4) = *(const float4*)&Bs[k][tn * 8 + 4];
#pragma unroll
            for (int i = 0; i < 8; i++)
#pragma unroll
                for (int j = 0; j < 8; j++)
                    acc[i][j] = fmaf(a[i], bb[j], acc[i][j]);
        }
    }

    if (TRANS) {
#pragma unroll
        for (int i = 0; i < 8; i++) {
            int row = m0 + tm * 8 + i;
            int b = row >> 12, l = row & 4095;
#pragma unroll
            for (int j = 0; j < 8; j++) {
                int col = n0 + tn * 8 + j;
                C[((size_t)b * N + col) * LSEQ + l] = acc[i][j];
            }
        }
    } else {
#pragma unroll
        for (int i = 0; i < 8; i++) {
            int row = m0 + tm * 8 + i;
            float4 v1 = make_float4(acc[i][0], acc[i][1], acc[i][2], acc[i][3]);
            float4 v2 = make_float4(acc[i][4], acc[i][5], acc[i][6], acc[i][7]);
            *(float4*)(C + (size_t)row * N + n0 + tn * 8)     = v1;
            *(float4*)(C + (size_t)row * N + n0 + tn * 8 + 4) = v2;
        }
    }
}

// ---------------- causal depthwise conv1d (k=4, left pad 3) + silu ----------------
__global__ __launch_bounds__(256)
void conv1d_silu_kernel(const float* __restrict__ xr, const float* __restrict__ w,
                        const float* __restrict__ bias, float* __restrict__ xs)
{
    int idx = blockIdx.x * 256 + threadIdx.x;       // over BATCH*LSEQ*DIN
    int d = idx & 255;
    int l = (idx >> 8) & 4095;
    int b = idx >> 20;
    const float* base = xr + (size_t)b * LSEQ * (2 * DIN) + d;
    float acc = bias[d];
#pragma unroll
    for (int j = 0; j < 4; j++) {
        int ll = l - 3 + j;
        if (ll >= 0) acc = fmaf(w[d * 4 + j], base[(size_t)ll * (2 * DIN)], acc);
    }
    float s = acc / (1.f + __expf(-acc));
    xs[idx] = s;
}

// ---------------- x_proj: xdbl[row, 40] = xs[row, 256] @ xw[256, 40] ----------------
__global__ __launch_bounds__(64)
void xproj_kernel(const float* __restrict__ xs, const float* __restrict__ xw,
                  float* __restrict__ xdbl)
{
    __shared__ float sx[DIN];
    int row = blockIdx.x;
    const float* p = xs + (size_t)row * DIN;
    for (int i = threadIdx.x; i < DIN; i += 64) sx[i] = p[i];
    __syncthreads();
    if (threadIdx.x < DTRANK + 2 * DSTATE) {
        float acc = 0.f;
#pragma unroll 8
        for (int k = 0; k < DIN; k++)
            acc = fmaf(sx[k], xw[k * (DTRANK + 2 * DSTATE) + threadIdx.x], acc);
        xdbl[(size_t)row * (DTRANK + 2 * DSTATE) + threadIdx.x] = acc;
    }
}

// ---------------- delta = softplus(xdbl[:, :8] @ dtw + dtb) ----------------
__global__ __launch_bounds__(256)
void delta_kernel(const float* __restrict__ xdbl, const float* __restrict__ dtw,
                  const float* __restrict__ dtb, float* __restrict__ delta)
{
    int idx = blockIdx.x * 256 + threadIdx.x;
    int d = idx & 255;
    int row = idx >> 8;
    const float* xd = xdbl + (size_t)row * (DTRANK + 2 * DSTATE);
    float pre = dtb[d];
#pragma unroll
    for (int r = 0; r < DTRANK; r++)
        pre = fmaf(xd[r], dtw[r * DIN + d], pre);
    float sp = (pre > 20.f) ? pre : log1pf(expf(pre));
    delta[idx] = sp;
}

// ---------------- selective scan: 2 (b,d) pairs per warp, 16 lanes per pair --------
__global__ __launch_bounds__(256)
void scan_kernel(const float* __restrict__ delta, const float* __restrict__ u,
                 const float* __restrict__ xdbl, const float* __restrict__ A_log,
                 const float* __restrict__ Dp, float* __restrict__ y)
{
    int warp = (blockIdx.x * blockDim.x + threadIdx.x) >> 5;
    int lane = threadIdx.x & 31;
    int half = lane >> 4;
    int n = lane & 15;
    int pair = warp * 2 + half;           // 0..1023
    int b = pair >> 8;
    int d = pair & 255;

    float A  = -__expf(A_log[d * DSTATE + n]);
    float Dv = Dp[d];

    const float* dl = delta + (size_t)b * LSEQ * DIN + d;
    const float* ul = u     + (size_t)b * LSEQ * DIN + d;
    const float* xb = xdbl  + (size_t)b * LSEQ * (DTRANK + 2 * DSTATE);
    float*       yo = y     + (size_t)b * LSEQ * DIN + d;

    float h = 0.f;
    for (int t = 0; t < LSEQ; t++) {
        float dt = dl[(size_t)t * DIN];
        float ut = ul[(size_t)t * DIN];
        float Bn = xb[(size_t)t * 40 + DTRANK + n];
        float Cn = xb[(size_t)t * 40 + DTRANK + DSTATE + n];
        float dA = __expf(dt * A);
        h = fmaf(dA, h, dt * ut * Bn);
        float yv = h * Cn;
        yv += __shfl_xor_sync(0xffffffffu, yv, 8);
        yv += __shfl_xor_sync(0xffffffffu, yv, 4);
        yv += __shfl_xor_sync(0xffffffffu, yv, 2);
        yv += __shfl_xor_sync(0xffffffffu, yv, 1);
        if (n == 0) yo[(size_t)t * DIN] = fmaf(ut, Dv, yv);
    }
}

// ---------------- gating: g = y * silu(res) ----------------
__global__ __launch_bounds__(256)
void gate_kernel(const float* __restrict__ y, const float* __restrict__ xr,
                 float* __restrict__ g)
{
    int idx = blockIdx.x * 256 + threadIdx.x;
    int k = idx & 255;
    int row = idx >> 8;
    float r = xr[(size_t)row * (2 * DIN) + DIN + k];
    float s = r / (1.f + __expf(-r));
    g[idx] = y[idx] * s;
}

// ---------------- launch ----------------
extern "C" void kernel_launch(void* const* d_in, const int* in_sizes, int n_in,
                              void* d_out, int out_size)
{
    const float* x         = (const float*)d_in[0];
    const float* conv1_w   = (const float*)d_in[1];
    const float* conv1_b   = (const float*)d_in[2];
    const float* conv2_w   = (const float*)d_in[3];
    const float* conv2_b   = (const float*)d_in[4];
    const float* ln_g      = (const float*)d_in[5];
    const float* ln_b      = (const float*)d_in[6];
    const float* in_proj_w = (const float*)d_in[7];
    const float* conv1d_w  = (const float*)d_in[8];
    const float* conv1d_b  = (const float*)d_in[9];
    const float* x_proj_w  = (const float*)d_in[10];
    const float* dt_proj_w = (const float*)d_in[11];
    const float* dt_proj_b = (const float*)d_in[12];
    const float* A_log     = (const float*)d_in[13];
    const float* Dp        = (const float*)d_in[14];
    const float* out_proj_w= (const float*)d_in[15];
    float* out = (float*)d_out;

    Scratch* s = nullptr;
    cudaGetSymbolAddress((void**)&s, g_scratch);

    // 1) conv1: (4,128,64,64) -> (4,256,64,64)
    conv3x3_kernel<DIM, DIN><<<dim3(WW / 32, HH / 16, BATCH * (DIN / 16)), 256>>>(
        x, conv1_w, conv1_b, s->h1);
    // 2) inorm + leaky
    inorm_lrelu_kernel<<<BATCH * DIN, 256>>>(s->h1, s->h1, nullptr);
    // 3) conv2: (4,256,64,64) -> (4,128,64,64)
    conv3x3_kernel<DIN, DIM><<<dim3(WW / 32, HH / 16, BATCH * (DIM / 16)), 256>>>(
        s->h1, conv2_w, conv2_b, s->h2);
    // 4) inorm + leaky + input residual
    inorm_lrelu_kernel<<<BATCH * DIM, 256>>>(s->h2, s->h2, x);
    // 5) layernorm over channels, transpose to (b*l, c)
    layernorm_kernel<<<BATCH * LSEQ / 8, 256>>>(s->h2, ln_g, ln_b, s->t);
    // 6) in_proj GEMM: (16384,128)@(128,512)
    gemm128_kernel<0><<<dim3(BATCH * LSEQ / 128, (2 * DIN) / 128), 256>>>(
        s->t, in_proj_w, s->xr, BATCH * LSEQ, 2 * DIN, DIM);
    // 7) causal depthwise conv1d + silu
    conv1d_silu_kernel<<<BATCH * LSEQ * DIN / 256, 256>>>(s->xr, conv1d_w, conv1d_b, s->xs);
    // 8) x_proj
    xproj_kernel<<<BATCH * LSEQ, 64>>>(s->xs, x_proj_w, s->xdbl);
    // 9) delta = softplus(dt_proj)
    delta_kernel<<<BATCH * LSEQ * DIN / 256, 256>>>(s->xdbl, dt_proj_w, dt_proj_b, s->delta);
    // 10) selective scan
    scan_kernel<<<64, 256>>>(s->delta, s->xs, s->xdbl, A_log, Dp, s->y);
    // 11) gating y * silu(res)
    gate_kernel<<<BATCH * LSEQ * DIN / 256, 256>>>(s->y, s->xr, s->gated);
    // 12) out_proj GEMM + transpose to NCHW output
    gemm128_kernel<1><<<dim3(BATCH * LSEQ / 128, DIM / 128), 256>>>(
        s->gated, out_proj_w, out, BATCH * LSEQ, DIM, DIN);
}

// round 2
// speedup vs baseline: 1.1243x; 1.1243x over previous
#include <cuda_runtime.h>
#include <cuda_bf16.h>
#include <cstdint>
#include <cstddef>

#define BATCH 4
#define DIM   128
#define DIN   256
#define HH    64
#define WW    64
#define HW    4096
#define LSEQ  4096
#define DSTATE 16
#define DTRANK 8
#define EPSV  1e-5f
#define SLOPE 0.01f

#define NCH   4          // scan chunks
#define CHLEN (LSEQ/NCH) // 1024
#define NPAIR (BATCH*DIN) // 1024 (b,d) pairs

typedef unsigned long long ull;

// ---------------- f32x2 helpers (Blackwell FFMA2) ----------------
__device__ __forceinline__ ull pack2(float lo, float hi) {
    ull r; asm("mov.b64 %0, {%1, %2};" : "=l"(r) : "f"(lo), "f"(hi)); return r;
}
__device__ __forceinline__ void unpack2(ull p, float& lo, float& hi) {
    asm("mov.b64 {%0, %1}, %2;" : "=f"(lo), "=f"(hi) : "l"(p));
}
__device__ __forceinline__ ull ffma2(ull a, ull b, ull c) {
    ull d; asm("fma.rn.f32x2 %0, %1, %2, %3;" : "=l"(d) : "l"(a), "l"(b), "l"(c)); return d;
}

// ---------------- scratch ----------------
struct Scratch {
    float h1[BATCH * DIN * HW];
    float h2[BATCH * DIM * HW];
    float t [BATCH * LSEQ * DIM];
    float xr[BATCH * LSEQ * 2*DIN];
    float xs[BATCH * LSEQ * DIN];        // (b,l,d) for xproj / delta kernel
    float xsT[NPAIR * LSEQ];             // (b,d,t) for scan
    float xdbl[BATCH * LSEQ * (DTRANK + 2*DSTATE)];
    float deltaT[NPAIR * LSEQ];          // (b,d,t)
    float duT[NPAIR * LSEQ];             // delta*u, (b,d,t)
    float yT[NPAIR * LSEQ];              // (b,d,t)
    float gated[BATCH * LSEQ * DIN];
    float chA[(NCH-1) * NPAIR * DSTATE];
    float chH[(NCH-1) * NPAIR * DSTATE];
    float hst[NCH * NPAIR * DSTATE];
};
__device__ Scratch g_scratch;

// ---------------- conv2d 3x3 pad 1, f32x2 inner ----------------
// 32x32 pixel tile, 8 output channels/block, 4 pixels/thread (rows ty+{0,8,16,24}),
// accumulators packed as f32x2 over row pairs (r, r+16); weights duplicated in smem.
template<int CIN, int COUT>
__global__ __launch_bounds__(256, 2)
void conv3x3_f2_kernel(const float* __restrict__ x, const float* __restrict__ w,
                       const float* __restrict__ bias, float* __restrict__ out)
{
    constexpr int TW = 32, TH = 32, OCPB = 8, CIC = 8;
    __shared__ float  sx[CIC][TH + 2][TW + 4];   // [8][34][36]
    __shared__ float2 sw2[OCPB][CIC][9];         // duplicated weights

    const int tid = threadIdx.x;
    const int tx = tid & 31, ty = tid >> 5;      // ty 0..7
    const int bx0 = blockIdx.x * TW, by0 = blockIdx.y * TH;
    const int bz = blockIdx.z;
    const int b  = bz / (COUT / OCPB);
    const int oc0 = (bz % (COUT / OCPB)) * OCPB;
    const float* xb = x + (size_t)b * CIN * HW;

    ull acc[OCPB][2];
#pragma unroll
    for (int i = 0; i < OCPB; i++) { acc[i][0] = 0ull; acc[i][1] = 0ull; }

    for (int c0 = 0; c0 < CIN; c0 += CIC) {
        __syncthreads();
        for (int idx = tid; idx < CIC * 34 * 34; idx += 256) {
            int ci  = idx / (34 * 34);
            int rem = idx % (34 * 34);
            int py  = rem / 34, px = rem % 34;
            int gy = by0 + py - 1, gx = bx0 + px - 1;
            float v = 0.f;
            if ((unsigned)gy < (unsigned)HH && (unsigned)gx < (unsigned)WW)
                v = xb[((size_t)(c0 + ci) * HH + gy) * WW + gx];
            sx[ci][py][px] = v;
        }
        for (int idx = tid; idx < OCPB * CIC * 9; idx += 256) {
            int oc = idx / (CIC * 9);
            int r  = idx % (CIC * 9);
            int ci = r / 9, tap = r % 9;
            float wv = w[((size_t)(oc0 + oc) * CIN + c0 + ci) * 9 + tap];
            sw2[oc][ci][tap] = make_float2(wv, wv);
        }
        __syncthreads();

#pragma unroll
        for (int ci = 0; ci < CIC; ci++) {
            ull xp[9][2];
#pragma unroll
            for (int i = 0; i < 3; i++)
#pragma unroll
                for (int j = 0; j < 3; j++) {
                    float a0 = sx[ci][ty      + i][tx + j];
                    float a1 = sx[ci][ty + 8  + i][tx + j];
                    float a2 = sx[ci][ty + 16 + i][tx + j];
                    float a3 = sx[ci][ty + 24 + i][tx + j];
                    xp[i * 3 + j][0] = pack2(a0, a2);
                    xp[i * 3 + j][1] = pack2(a1, a3);
                }
#pragma unroll
            for (int oc = 0; oc < OCPB; oc++) {
#pragma unroll
                for (int tap = 0; tap < 9; tap++) {
                    ull w2 = *(const ull*)&sw2[oc][ci][tap];
                    acc[oc][0] = ffma2(xp[tap][0], w2, acc[oc][0]);
                    acc[oc][1] = ffma2(xp[tap][1], w2, acc[oc][1]);
                }
            }
        }
    }

    float* ob = out + (size_t)b * COUT * HW;
#pragma unroll
    for (int oc = 0; oc < OCPB; oc++) {
        float bv = bias[oc0 + oc];
        float r0, r16, r8, r24;
        unpack2(acc[oc][0], r0, r16);
        unpack2(acc[oc][1], r8, r24);
        size_t base = ((size_t)(oc0 + oc) * HH) * WW + bx0 + tx;
        ob[base + (size_t)(by0 + ty)      * WW] = r0  + bv;
        ob[base + (size_t)(by0 + ty + 8)  * WW] = r8  + bv;
        ob[base + (size_t)(by0 + ty + 16) * WW] = r16 + bv;
        ob[base + (size_t)(by0 + ty + 24) * WW] = r24 + bv;
    }
}

// ---------------- instance norm + leaky residual ----------------
__global__ __launch_bounds__(256)
void inorm_lrelu_kernel(const float* __restrict__ in, float* __restrict__ out,
                        const float* __restrict__ resid)
{
    __shared__ float s1[256], s2[256];
    const size_t base = (size_t)blockIdx.x * HW;
    const float* p = in + base;
    float v[16];
    float sum = 0.f, sq = 0.f;
#pragma unroll
    for (int i = 0; i < 16; i++) {
        v[i] = p[threadIdx.x + i * 256];
        sum += v[i]; sq += v[i] * v[i];
    }
    s1[threadIdx.x] = sum; s2[threadIdx.x] = sq;
    __syncthreads();
    for (int off = 128; off; off >>= 1) {
        if (threadIdx.x < off) {
            s1[threadIdx.x] += s1[threadIdx.x + off];
            s2[threadIdx.x] += s2[threadIdx.x + off];
        }
        __syncthreads();
    }
    float mean = s1[0] * (1.f / HW);
    float var  = s2[0] * (1.f / HW) - mean * mean;
    float rstd = rsqrtf(var + EPSV);
    float* o = out + base;
    const float* r = resid ? resid + base : nullptr;
#pragma unroll
    for (int i = 0; i < 16; i++) {
        float xv = v[i];
        float lr = xv > 0.f ? xv : SLOPE * xv;
        float val = (xv - mean) * rstd + lr;
        if (r) val += r[threadIdx.x + i * 256];
        o[threadIdx.x + i * 256] = val;
    }
}

// ---------------- layernorm over channels + transpose to (b*l, c) ----------------
__global__ __launch_bounds__(256)
void layernorm_kernel(const float* __restrict__ h, const float* __restrict__ g,
                      const float* __restrict__ beta, float* __restrict__ t)
{
    int warp = threadIdx.x >> 5, lane = threadIdx.x & 31;
    int row = blockIdx.x * 8 + warp;
    int b = row >> 12, l = row & 4095;
    const float* hb = h + (size_t)b * DIM * HW + l;
    float v[4];
    float sum = 0.f, sq = 0.f;
#pragma unroll
    for (int k = 0; k < 4; k++) {
        v[k] = hb[(size_t)(lane + 32 * k) * HW];
        sum += v[k]; sq += v[k] * v[k];
    }
#pragma unroll
    for (int off = 16; off; off >>= 1) {
        sum += __shfl_xor_sync(0xffffffffu, sum, off);
        sq  += __shfl_xor_sync(0xffffffffu, sq,  off);
    }
    float mean = sum * (1.f / DIM);
    float var  = sq * (1.f / DIM) - mean * mean;
    float rstd = rsqrtf(var + EPSV);
    float* to = t + (size_t)row * DIM;
#pragma unroll
    for (int k = 0; k < 4; k++) {
        int c = lane + 32 * k;
        to[c] = (v[k] - mean) * rstd * g[c] + beta[c];
    }
}

// ---------------- fp32 SGEMM with f32x2 inner ----------------
template<int TRANS>
__global__ __launch_bounds__(256)
void gemm128_f2_kernel(const float* __restrict__ A, const float* __restrict__ Bw,
                       float* __restrict__ C, int M, int N, int K)
{
    __shared__ ull   As2[8][128];   // A duplicated: (a,a)
    __shared__ float Bs[8][128];
    const int tid = threadIdx.x;
    const int tm = tid >> 4, tn = tid & 15;
    const int m0 = blockIdx.x * 128, n0 = blockIdx.y * 128;

    ull acc[8][4];
#pragma unroll
    for (int i = 0; i < 8; i++)
#pragma unroll
        for (int j = 0; j < 4; j++) acc[i][j] = 0ull;

    const int ar = tid >> 1, ak = (tid & 1) * 4;
    const int bk = tid >> 5, bn = (tid & 31) * 4;

    for (int k0 = 0; k0 < K; k0 += 8) {
        float4 av = *(const float4*)(A + (size_t)(m0 + ar) * K + k0 + ak);
        float4 bv = *(const float4*)(Bw + (size_t)(k0 + bk) * N + n0 + bn);
        __syncthreads();
        As2[ak + 0][ar] = pack2(av.x, av.x);
        As2[ak + 1][ar] = pack2(av.y, av.y);
        As2[ak + 2][ar] = pack2(av.z, av.z);
        As2[ak + 3][ar] = pack2(av.w, av.w);
        *(float4*)&Bs[bk][bn] = bv;
        __syncthreads();
#pragma unroll
        for (int k = 0; k < 8; k++) {
            ull a2[8], b2[4];
#pragma unroll
            for (int i = 0; i < 8; i++) a2[i] = As2[k][tm * 8 + i];
#pragma unroll
            for (int j = 0; j < 4; j++) b2[j] = *(const ull*)&Bs[k][tn * 8 + 2 * j];
#pragma unroll
            for (int i = 0; i < 8; i++)
#pragma unroll
                for (int j = 0; j < 4; j++)
                    acc[i][j] = ffma2(a2[i], b2[j], acc[i][j]);
        }
    }

#pragma unroll
    for (int i = 0; i < 8; i++) {
        float c[8];
#pragma unroll
        for (int j = 0; j < 4; j++) unpack2(acc[i][j], c[2 * j], c[2 * j + 1]);
        int row = m0 + tm * 8 + i;
        if (TRANS) {
            int b = row >> 12, l = row & 4095;
#pragma unroll
            for (int j = 0; j < 8; j++) {
                int col = n0 + tn * 8 + j;
                C[((size_t)b * N + col) * LSEQ + l] = c[j];
            }
        } else {
            *(float4*)(C + (size_t)row * N + n0 + tn * 8)     = make_float4(c[0], c[1], c[2], c[3]);
            *(float4*)(C + (size_t)row * N + n0 + tn * 8 + 4) = make_float4(c[4], c[5], c[6], c[7]);
        }
    }
}

// ---------------- causal depthwise conv1d (k=4) + silu, dual-layout output ------
// block: 32 d x 32 t tile; threads (32,8)
__global__ __launch_bounds__(256)
void conv1d_silu_T_kernel(const float* __restrict__ xr, const float* __restrict__ w,
                          const float* __restrict__ bias,
                          float* __restrict__ xs, float* __restrict__ xsT)
{
    __shared__ float st[32][33];
    const int tx = threadIdx.x & 31, ty = threadIdx.x >> 5;
    const int t0 = blockIdx.x * 32, d0 = blockIdx.y * 32, b = blockIdx.z;
    const int d = d0 + tx;
    float w0 = w[d * 4 + 0], w1 = w[d * 4 + 1], w2 = w[d * 4 + 2], w3 = w[d * 4 + 3];
    float bv = bias[d];
    const float* xrb = xr + (size_t)b * LSEQ * (2 * DIN) + d;
#pragma unroll
    for (int k = 0; k < 4; k++) {
        int t = t0 + ty + 8 * k;
        float acc = bv;
        if (t - 3 >= 0) acc = fmaf(w0, xrb[(size_t)(t - 3) * (2 * DIN)], acc);
        if (t - 2 >= 0) acc = fmaf(w1, xrb[(size_t)(t - 2) * (2 * DIN)], acc);
        if (t - 1 >= 0) acc = fmaf(w2, xrb[(size_t)(t - 1) * (2 * DIN)], acc);
        acc = fmaf(w3, xrb[(size_t)t * (2 * DIN)], acc);
        float s = acc / (1.f + __expf(-acc));
        xs[((size_t)b * LSEQ + t) * DIN + d] = s;
        st[tx][ty + 8 * k] = s;
    }
    __syncthreads();
#pragma unroll
    for (int k = 0; k < 4; k++) {
        int dd = d0 + ty + 8 * k;
        xsT[((size_t)(b * DIN + dd)) * LSEQ + t0 + tx] = st[ty + 8 * k][tx];
    }
}

// ---------------- x_proj: xdbl[row, 40] = xs[row, 256] @ xw[256, 40] ----------------
__global__ __launch_bounds__(64)
void xproj_kernel(const float* __restrict__ xs, const float* __restrict__ xw,
                  float* __restrict__ xdbl)
{
    __shared__ float sx[DIN];
    int row = blockIdx.x;
    const float* p = xs + (size_t)row * DIN;
    for (int i = threadIdx.x; i < DIN; i += 64) sx[i] = p[i];
    __syncthreads();
    if (threadIdx.x < DTRANK + 2 * DSTATE) {
        float acc = 0.f;
#pragma unroll 8
        for (int k = 0; k < DIN; k++)
            acc = fmaf(sx[k], xw[k * (DTRANK + 2 * DSTATE) + threadIdx.x], acc);
        xdbl[(size_t)row * (DTRANK + 2 * DSTATE) + threadIdx.x] = acc;
    }
}

// ---------------- delta = softplus(dt_proj), write deltaT and duT (transposed) ----
// block: 32 d x 32 t tile; threads (32,8)
__global__ __launch_bounds__(256)
void delta_du_T_kernel(const float* __restrict__ xdbl, const float* __restrict__ dtw,
                       const float* __restrict__ dtb, const float* __restrict__ xs,
                       float* __restrict__ deltaT, float* __restrict__ duT)
{
    __shared__ float sdel[32][33], sdu[32][33];
    const int tx = threadIdx.x & 31, ty = threadIdx.x >> 5;
    const int t0 = blockIdx.x * 32, d0 = blockIdx.y * 32, b = blockIdx.z;
    const int d = d0 + tx;
    float wr[DTRANK];
#pragma unroll
    for (int r = 0; r < DTRANK; r++) wr[r] = dtw[r * DIN + d];
    float bvb = dtb[d];
#pragma unroll
    for (int k = 0; k < 4; k++) {
        int t = t0 + ty + 8 * k;
        const float* xd = xdbl + (size_t)(b * LSEQ + t) * (DTRANK + 2 * DSTATE);
        float pre = bvb;
#pragma unroll
        for (int r = 0; r < DTRANK; r++) pre = fmaf(xd[r], wr[r], pre);
        float sp = (pre > 20.f) ? pre : log1pf(expf(pre));
        float u  = xs[((size_t)b * LSEQ + t) * DIN + d];
        sdel[tx][ty + 8 * k] = sp;
        sdu[tx][ty + 8 * k]  = sp * u;
    }
    __syncthreads();
#pragma unroll
    for (int k = 0; k < 4; k++) {
        int dd = d0 + ty + 8 * k;
        size_t o = ((size_t)(b * DIN + dd)) * LSEQ + t0 + tx;
        deltaT[o] = sdel[ty + 8 * k][tx];
        duT[o]    = sdu[ty + 8 * k][tx];
    }
}

// ---------------- scan pass 1: per-chunk (prod dA, local h) for chunks 0..NCH-2 ----
__global__ __launch_bounds__(256)
void scan_p1_kernel(const float* __restrict__ deltaT, const float* __restrict__ duT,
                    const float* __restrict__ xdbl, const float* __restrict__ A_log,
                    float* __restrict__ chA, float* __restrict__ chH)
{
    int gw = (blockIdx.x * blockDim.x + threadIdx.x) >> 5;
    int lane = threadIdx.x & 31;
    int half = lane >> 4, n = lane & 15;
    int chunk = gw >> 9;               // 0..NCH-2
    int wp = gw & 511;
    int pair = wp * 2 + half;
    int b = pair >> 8, d = pair & 255;
    int t0 = chunk * CHLEN;

    float A = -__expf(A_log[d * DSTATE + n]);
    const float* dl = deltaT + (size_t)(b * DIN + d) * LSEQ + t0;
    const float* du = duT    + (size_t)(b * DIN + d) * LSEQ + t0;
    const float* xb = xdbl + ((size_t)b * LSEQ + t0) * 40;

    float h = 0.f, pA = 1.f;
    for (int t = 0; t < CHLEN; t++) {
        float dt  = dl[t];
        float duv = du[t];
        float Bn  = xb[t * 40 + DTRANK + n];
        float a = __expf(dt * A);
        pA *= a;
        h = fmaf(a, h, duv * Bn);
    }
    int idx = (chunk * NPAIR + pair) * DSTATE + n;
    chA[idx] = pA;
    chH[idx] = h;
}

// ---------------- scan pass 2: chunk carry fixup ----------------
__global__ __launch_bounds__(256)
void scan_p2_kernel(const float* __restrict__ chA, const float* __restrict__ chH,
                    float* __restrict__ hst)
{
    int i = blockIdx.x * 256 + threadIdx.x;  // pair*16+n, 0..16383
    float h = 0.f;
    hst[i] = 0.f;
#pragma unroll
    for (int c = 0; c < NCH - 1; c++) {
        h = fmaf(chA[c * NPAIR * DSTATE + i], h, chH[c * NPAIR * DSTATE + i]);
        hst[(c + 1) * NPAIR * DSTATE + i] = h;
    }
}

// ---------------- scan pass 3: full scan per chunk with correct h0, emit yT --------
__global__ __launch_bounds__(256)
void scan_p3_kernel(const float* __restrict__ deltaT, const float* __restrict__ duT,
                    const float* __restrict__ xsT, const float* __restrict__ xdbl,
                    const float* __restrict__ A_log, const float* __restrict__ Dp,
                    const float* __restrict__ hst, float* __restrict__ yT)
{
    __shared__ float sy[8][2][32];
    int gw = (blockIdx.x * blockDim.x + threadIdx.x) >> 5;
    int lane = threadIdx.x & 31;
    int wslot = threadIdx.x >> 5;
    int half = lane >> 4, n = lane & 15;
    int chunk = gw >> 9;               // 0..NCH-1
    int wp = gw & 511;
    int pair = wp * 2 + half;
    int b = pair >> 8, d = pair & 255;
    int t0 = chunk * CHLEN;

    float A = -__expf(A_log[d * DSTATE + n]);
    const float* dl = deltaT + (size_t)(b * DIN + d) * LSEQ + t0;
    const float* du = duT    + (size_t)(b * DIN + d) * LSEQ + t0;
    const float* xb = xdbl + ((size_t)b * LSEQ + t0) * 40;
    float h = hst[(chunk * NPAIR + pair) * DSTATE + n];

    // both pairs of this warp (for the flush)
    int dp0 = (wp * 2) & 255;
    int bb  = (wp * 2) >> 8;
    float Dv0 = Dp[dp0], Dv1 = Dp[dp0 + 1];
    const float* u0p = xsT + (size_t)(bb * DIN + dp0)     * LSEQ + t0;
    const float* u1p = xsT + (size_t)(bb * DIN + dp0 + 1) * LSEQ + t0;
    float* y0p = yT + (size_t)(bb * DIN + dp0)     * LSEQ + t0;
    float* y1p = yT + (size_t)(bb * DIN + dp0 + 1) * LSEQ + t0;

    for (int t = 0; t < CHLEN; t++) {
        float dt  = dl[t];
        float duv = du[t];
        float Bn  = xb[t * 40 + DTRANK + n];
        float Cn  = xb[t * 40 + DTRANK + DSTATE + n];
        float a = __expf(dt * A);
        h = fmaf(a, h, duv * Bn);
        float yv = h * Cn;
        yv += __shfl_xor_sync(0xffffffffu, yv, 8);
        yv += __shfl_xor_sync(0xffffffffu, yv, 4);
        yv += __shfl_xor_sync(0xffffffffu, yv, 2);
        yv += __shfl_xor_sync(0xffffffffu, yv, 1);
        if (n == 0) sy[wslot][half][t & 31] = yv;
        if ((t & 31) == 31) {
            __syncwarp();
            int tb = t & ~31;
            y0p[tb + lane] = fmaf(u0p[tb + lane], Dv0, sy[wslot][0][lane]);
            y1p[tb + lane] = fmaf(u1p[tb + lane], Dv1, sy[wslot][1][lane]);
            __syncwarp();
        }
    }
}

// ---------------- gate: gated[b,t,d] = yT[b,d,t] * silu(res[b,t,d]) ----------------
// block: 32 d x 32 t tile
__global__ __launch_bounds__(256)
void gateT_kernel(const float* __restrict__ yT, const float* __restrict__ xr,
                  float* __restrict__ gated)
{
    __shared__ float sy[32][33];
    const int tx = threadIdx.x & 31, ty = threadIdx.x >> 5;
    const int t0 = blockIdx.x * 32, d0 = blockIdx.y * 32, b = blockIdx.z;
#pragma unroll
    for (int k = 0; k < 4; k++) {
        int dd = d0 + ty + 8 * k;
        sy[ty + 8 * k][tx] = yT[((size_t)(b * DIN + dd)) * LSEQ + t0 + tx];
    }
    __syncthreads();
#pragma unroll
    for (int k = 0; k < 4; k++) {
        int t = t0 + ty + 8 * k;
        float r = xr[((size_t)b * LSEQ + t) * (2 * DIN) + DIN + d0 + tx];
        float s = r / (1.f + __expf(-r));
        gated[((size_t)b * LSEQ + t) * DIN + d0 + tx] = sy[tx][ty + 8 * k] * s;
    }
}

// ---------------- launch ----------------
extern "C" void kernel_launch(void* const* d_in, const int* in_sizes, int n_in,
                              void* d_out, int out_size)
{
    const float* x         = (const float*)d_in[0];
    const float* conv1_w   = (const float*)d_in[1];
    const float* conv1_b   = (const float*)d_in[2];
    const float* conv2_w   = (const float*)d_in[3];
    const float* conv2_b   = (const float*)d_in[4];
    const float* ln_g      = (const float*)d_in[5];
    const float* ln_b      = (const float*)d_in[6];
    const float* in_proj_w = (const float*)d_in[7];
    const float* conv1d_w  = (const float*)d_in[8];
    const float* conv1d_b  = (const float*)d_in[9];
    const float* x_proj_w  = (const float*)d_in[10];
    const float* dt_proj_w = (const float*)d_in[11];
    const float* dt_proj_b = (const float*)d_in[12];
    const float* A_log     = (const float*)d_in[13];
    const float* Dp        = (const float*)d_in[14];
    const float* out_proj_w= (const float*)d_in[15];
    float* out = (float*)d_out;

    Scratch* s = nullptr;
    cudaGetSymbolAddress((void**)&s, g_scratch);

    // 1) conv1: (4,128,64,64) -> (4,256,64,64)
    conv3x3_f2_kernel<DIM, DIN><<<dim3(WW / 32, HH / 32, BATCH * (DIN / 8)), 256>>>(
        x, conv1_w, conv1_b, s->h1);
    // 2) inorm + leaky
    inorm_lrelu_kernel<<<BATCH * DIN, 256>>>(s->h1, s->h1, nullptr);
    // 3) conv2
    conv3x3_f2_kernel<DIN, DIM><<<dim3(WW / 32, HH / 32, BATCH * (DIM / 8)), 256>>>(
        s->h1, conv2_w, conv2_b, s->h2);
    // 4) inorm + leaky + residual
    inorm_lrelu_kernel<<<BATCH * DIM, 256>>>(s->h2, s->h2, x);
    // 5) layernorm + transpose to (b*l, c)
    layernorm_kernel<<<BATCH * LSEQ / 8, 256>>>(s->h2, ln_g, ln_b, s->t);
    // 6) in_proj GEMM
    gemm128_f2_kernel<0><<<dim3(BATCH * LSEQ / 128, (2 * DIN) / 128), 256>>>(
        s->t, in_proj_w, s->xr, BATCH * LSEQ, 2 * DIN, DIM);
    // 7) depthwise conv1d + silu (row + transposed layouts)
    conv1d_silu_T_kernel<<<dim3(LSEQ / 32, DIN / 32, BATCH), 256>>>(
        s->xr, conv1d_w, conv1d_b, s->xs, s->xsT);
    // 8) x_proj
    xproj_kernel<<<BATCH * LSEQ, 64>>>(s->xs, x_proj_w, s->xdbl);
    // 9) delta + du, transposed
    delta_du_T_kernel<<<dim3(LSEQ / 32, DIN / 32, BATCH), 256>>>(
        s->xdbl, dt_proj_w, dt_proj_b, s->xs, s->deltaT, s->duT);
    // 10) chunked selective scan (3 passes)
    scan_p1_kernel<<<(NCH - 1) * 512 * 32 / 256, 256>>>(
        s->deltaT, s->duT, s->xdbl, A_log, s->chA, s->chH);
    scan_p2_kernel<<<NPAIR * DSTATE / 256, 256>>>(s->chA, s->chH, s->hst);
    scan_p3_kernel<<<NCH * 512 * 32 / 256, 256>>>(
        s->deltaT, s->duT, s->xsT, s->xdbl, A_log, Dp, s->hst, s->yT);
    // 11) gate
    gateT_kernel<<<dim3(LSEQ / 32, DIN / 32, BATCH), 256>>>(s->yT, s->xr, s->gated);
    // 12) out_proj GEMM + NCHW transpose
    gemm128_f2_kernel<1><<<dim3(BATCH * LSEQ / 128, DIM / 128), 256>>>(
        s->gated, out_proj_w, out, BATCH * LSEQ, DIM, DIN);
}